// round 5
// baseline (speedup 1.0000x reference)
#include <cuda_runtime.h>
#include <math.h>

#define HW 224
#define C 96
#define T 49
#define CQKV 288
#define HID 384
#define HCH 192

#define XSTR 96
#define QSTR 98
#define KSTR 98
#define VSTR 96
#define SSTR 52
#define HSTR 192

#define OFF_Q 4704            /* 49*96  */
#define OFF_K 9506            /* +49*98 */
#define OFF_V 14308           /* +49*98 */
#define OFF_S 0               /* reuses XLN region */
#define OFF_H OFF_K           /* hidden reuses K+V regions, 50x192 */
#define SMEM_FLOATS (OFF_V + 50*VSTR)   /* 19108 */
#define SMEM_BYTES (SMEM_FLOATS * 4)    /* 76432 */

typedef unsigned long long u64t;

__device__ __forceinline__ u64t splat2(float a){
    u64t r; asm("mov.b64 %0, {%1,%1};" : "=l"(r) : "f"(a)); return r;
}
__device__ __forceinline__ u64t pk2(float a, float b){
    u64t r; asm("mov.b64 %0, {%1,%2};" : "=l"(r) : "f"(a), "f"(b)); return r;
}
__device__ __forceinline__ u64t fma2(u64t a, u64t b, u64t c){
    u64t d; asm("fma.rn.f32x2 %0, %1, %2, %3;" : "=l"(d) : "l"(a), "l"(b), "l"(c)); return d;
}
__device__ __forceinline__ void up2(u64t x, float& l, float& h){
    asm("mov.b64 {%0,%1}, %2;" : "=f"(l), "=f"(h) : "l"(x));
}

__global__ __launch_bounds__(256, 2)
void swin_fused(const float* __restrict__ x, const float* __restrict__ qkv_w,
                const float* __restrict__ ln_w, const float* __restrict__ ln_b,
                const float* __restrict__ w1, const float* __restrict__ b1,
                const float* __restrict__ w2, const float* __restrict__ b2,
                float* __restrict__ out)
{
    extern __shared__ float sm[];
    float* XLN = sm;                 // [49][96]; later S [49][52]
    float* Qs  = sm + OFF_Q;         // [49][98]; later attn_out
    float* Ks  = sm + OFF_K;         // [49][98]
    float* Vs  = sm + OFF_V;         // [50][96] (row 49 zeroed)
    float* Ss  = sm + OFF_S;
    float* HB  = sm + OFF_H;         // [50][192] (row 49 zeroed)

    const int tid  = threadIdx.x;
    const int widx = blockIdx.x;
    const int b  = widx >> 10;
    const int wh = (widx >> 5) & 31;
    const int ww = widx & 31;
    const size_t base = ((size_t)(b*HW + wh*7) * HW + (size_t)(ww*7)) * C;

    // ---- load x window (49 x 96) ----
    for (int i = tid; i < T*24; i += 256) {
        int t = i / 24, v4 = i - t*24;
        int r = t / 7, s = t - r*7;
        float4 val = *(const float4*)(x + base + (size_t)(r*HW + s)*C + v4*4);
        *(float4*)(XLN + t*XSTR + v4*4) = val;
    }
    __syncthreads();

    // ---- layernorm ----
    {
        const int lane = tid & 31, warp = tid >> 5;
        const float lw0 = ln_w[lane], lw1 = ln_w[lane+32], lw2 = ln_w[lane+64];
        const float lb0 = ln_b[lane], lb1 = ln_b[lane+32], lb2 = ln_b[lane+64];
        for (int t = warp; t < T; t += 8) {
            float a0 = XLN[t*XSTR+lane], a1 = XLN[t*XSTR+lane+32], a2 = XLN[t*XSTR+lane+64];
            float sum = a0+a1+a2;
            float sq  = a0*a0 + a1*a1 + a2*a2;
            #pragma unroll
            for (int o = 16; o; o >>= 1) {
                sum += __shfl_xor_sync(0xffffffffu, sum, o);
                sq  += __shfl_xor_sync(0xffffffffu, sq , o);
            }
            float mu  = sum * (1.f/96.f);
            float var = fmaxf(sq * (1.f/96.f) - mu*mu, 0.f);
            float rs  = rsqrtf(var + 1e-5f);
            XLN[t*XSTR+lane]    = (a0-mu)*rs*lw0 + lb0;
            XLN[t*XSTR+lane+32] = (a1-mu)*rs*lw1 + lb1;
            XLN[t*XSTR+lane+64] = (a2-mu)*rs*lw2 + lb2;
        }
    }
    __syncthreads();

    // ---- QKV GEMM: [49x96]@[96x288], weights via LDG (L1), f32x2, 7x8 tile ----
    {
        const int cg = tid % 36, tg = tid / 36;     // tg<7 valid
        const int trow = (tg < 7 ? tg : 6) * 7;     // clamp to stay in-bounds
        u64t acc[7][4];
        #pragma unroll
        for (int i=0;i<7;i++)
            #pragma unroll
            for (int p=0;p<4;p++) acc[i][p] = 0ull;
        const float* wp_base = qkv_w + cg*8;
        #pragma unroll 4
        for (int cc = 0; cc < C; cc++) {
            float4 wa = *(const float4*)(wp_base + (size_t)cc*CQKV);
            float4 wb = *(const float4*)(wp_base + (size_t)cc*CQKV + 4);
            u64t w0 = pk2(wa.x, wa.y), w1v = pk2(wa.z, wa.w);
            u64t w2v = pk2(wb.x, wb.y), w3v = pk2(wb.z, wb.w);
            #pragma unroll
            for (int i=0;i<7;i++) {
                u64t xs = splat2(XLN[(trow+i)*XSTR + cc]);
                acc[i][0] = fma2(xs, w0, acc[i][0]);
                acc[i][1] = fma2(xs, w1v, acc[i][1]);
                acc[i][2] = fma2(xs, w2v, acc[i][2]);
                acc[i][3] = fma2(xs, w3v, acc[i][3]);
            }
        }
        if (tg < 7) {
            const int j0 = cg*8;
            float* dst; int jl; int str;
            if (j0 < 96)       { dst = Qs; jl = j0;        str = QSTR; }
            else if (j0 < 192) { dst = Ks; jl = j0 - 96;   str = KSTR; }
            else               { dst = Vs; jl = j0 - 192;  str = VSTR; }
            #pragma unroll
            for (int i=0;i<7;i++)
                #pragma unroll
                for (int p=0;p<4;p++) {
                    float l,h; up2(acc[i][p], l, h);
                    dst[(tg*7+i)*str + jl + 2*p]   = l;
                    dst[(tg*7+i)*str + jl + 2*p+1] = h;
                }
        }
    }
    // zero V row 49 (used by padded SV loop)
    if (tid < 48) *(u64t*)(Vs + 49*VSTR + tid*2) = 0ull;
    __syncthreads();

    // ---- logits S = Q K^T / sqrt(96) (into XLN region) ----
    {
        const float scale = 0.10206207261596577f;
        for (int u = tid; u < 343; u += 256) {
            int n = u / 7, mg = u - n*7;
            u64t a2[7];
            #pragma unroll
            for (int mm=0;mm<7;mm++) a2[mm] = 0ull;
            #pragma unroll 4
            for (int c = 0; c < C; c += 4) {
                const u64t* qp = (const u64t*)(Qs + n*QSTR + c);
                u64t q0 = qp[0], q1 = qp[1];
                #pragma unroll
                for (int mm=0;mm<7;mm++) {
                    const u64t* kp = (const u64t*)(Ks + (mg*7+mm)*KSTR + c);
                    a2[mm] = fma2(q0, kp[0], a2[mm]);
                    a2[mm] = fma2(q1, kp[1], a2[mm]);
                }
            }
            #pragma unroll
            for (int mm=0;mm<7;mm++) {
                float l,h; up2(a2[mm], l, h);
                Ss[n*SSTR + mg*7+mm] = (l+h)*scale;
            }
        }
    }
    __syncthreads();

    // ---- softmax rows (+ zero pad col 49) ----
    {
        const int lane = tid & 31, warp = tid >> 5;
        for (int n = warp; n < T; n += 8) {
            float v0 = Ss[n*SSTR + lane];
            float v1 = (lane < 17) ? Ss[n*SSTR + 32 + lane] : -3.0e38f;
            float m = fmaxf(v0, v1);
            #pragma unroll
            for (int o=16;o;o>>=1) m = fmaxf(m, __shfl_xor_sync(0xffffffffu, m, o));
            float e0 = __expf(v0 - m);
            float e1 = (lane < 17) ? __expf(v1 - m) : 0.f;
            float ssum = e0 + e1;
            #pragma unroll
            for (int o=16;o;o>>=1) ssum += __shfl_xor_sync(0xffffffffu, ssum, o);
            float inv = 1.f / ssum;
            Ss[n*SSTR + lane] = e0*inv;
            if (lane < 17) Ss[n*SSTR + 32 + lane] = e1*inv;
            if (lane == 17) Ss[n*SSTR + 49] = 0.f;
        }
    }
    __syncthreads();

    // ---- attn_out = S @ V -> Q region ----
    {
        const int cg = tid % 24, tg = tid / 24;   // tg<10, 5 rows each (rows 0..49)
        if (tg < 10) {
            u64t acc[5][4];
            #pragma unroll
            for (int i=0;i<5;i++)
                #pragma unroll
                for (int p=0;p<4;p++) acc[i][p] = 0ull;
            #pragma unroll 5
            for (int m = 0; m < 50; m += 2) {
                float4 va = *(float4*)(Vs + m*VSTR + cg*4);
                float4 vb = *(float4*)(Vs + (m+1)*VSTR + cg*4);
                u64t v0 = pk2(va.x, vb.x), v1 = pk2(va.y, vb.y);
                u64t v2 = pk2(va.z, vb.z), v3 = pk2(va.w, vb.w);
                #pragma unroll
                for (int i=0;i<5;i++) {
                    u64t s2 = *(const u64t*)(Ss + (tg*5+i)*SSTR + m);
                    acc[i][0] = fma2(s2, v0, acc[i][0]);
                    acc[i][1] = fma2(s2, v1, acc[i][1]);
                    acc[i][2] = fma2(s2, v2, acc[i][2]);
                    acc[i][3] = fma2(s2, v3, acc[i][3]);
                }
            }
            #pragma unroll
            for (int i=0;i<5;i++) {
                int t = tg*5 + i;
                float l0,h0,l1,h1,l2,h2,l3,h3;
                up2(acc[i][0], l0, h0); up2(acc[i][1], l1, h1);
                up2(acc[i][2], l2, h2); up2(acc[i][3], l3, h3);
                u64t* d = (u64t*)(Qs + t*QSTR + cg*4);
                d[0] = pk2(l0+h0, l1+h1);
                d[1] = pk2(l2+h2, l3+h3);
            }
        }
    }
    __syncthreads();

    // ---- MLP: weights via LDG, two hidden chunks of 192 ----
    const int cg6 = tid % 32, tg8 = tid / 32;      // w1 map: 6 cols x 7 rows
    const int cgf = tid % 24, tgf = tid / 24;      // w2 map: 4 cols x 5 rows (tgf<10)
    const int trow1 = (tg8 < 7 ? tg8 : 6) * 7;
    u64t facc[5][2];
    #pragma unroll
    for (int i=0;i<5;i++){ facc[i][0]=0ull; facc[i][1]=0ull; }

    for (int hc = 0; hc < 2; hc++) {
        const int j0 = hc * HCH;
        // --- hidden = gelu(attn_out @ w1[:, j0:j0+192] + b1) ---
        {
            u64t hacc[7][3];
            #pragma unroll
            for (int i=0;i<7;i++){ hacc[i][0]=0ull; hacc[i][1]=0ull; hacc[i][2]=0ull; }
            const float* w1p = w1 + j0 + cg6*6;
            #pragma unroll 4
            for (int cc = 0; cc < C; cc++) {
                const u64t* wp = (const u64t*)(w1p + (size_t)cc*HID);
                u64t w0 = wp[0], w1v = wp[1], w2v = wp[2];
                #pragma unroll
                for (int i=0;i<7;i++) {
                    u64t xs = splat2(Qs[(trow1+i)*QSTR + cc]);
                    hacc[i][0] = fma2(xs, w0, hacc[i][0]);
                    hacc[i][1] = fma2(xs, w1v, hacc[i][1]);
                    hacc[i][2] = fma2(xs, w2v, hacc[i][2]);
                }
            }
            if (tg8 < 7) {
                const float* bp = b1 + j0 + cg6*6;
                float bv[6];
                #pragma unroll
                for (int j=0;j<6;j++) bv[j] = bp[j];
                #pragma unroll
                for (int i=0;i<7;i++) {
                    float* hrow = HB + (tg8*7+i)*HSTR + cg6*6;
                    #pragma unroll
                    for (int p=0;p<3;p++) {
                        float l,h; up2(hacc[i][p], l, h);
                        float h0 = l + bv[2*p];
                        float h1 = h + bv[2*p+1];
                        hrow[2*p]   = 0.5f*h0*(1.f + erff(h0*0.70710678118654752f));
                        hrow[2*p+1] = 0.5f*h1*(1.f + erff(h1*0.70710678118654752f));
                    }
                }
            }
            if (tid < 96) *(u64t*)(HB + 49*HSTR + tid*2) = 0ull;  // zero hidden row 49
        }
        __syncthreads();
        // --- facc += hidden @ w2[j0:j0+192, :] ---
        if (tgf < 10) {
            const float* w2p = w2 + (size_t)j0*C + cgf*4;
            #pragma unroll 4
            for (int kk = 0; kk < HCH; kk++) {
                float4 wv = *(const float4*)(w2p + (size_t)kk*C);
                u64t w0 = pk2(wv.x, wv.y), w1v = pk2(wv.z, wv.w);
                #pragma unroll
                for (int i=0;i<5;i++) {
                    u64t hs = splat2(HB[(tgf*5+i)*HSTR + kk]);
                    facc[i][0] = fma2(hs, w0, facc[i][0]);
                    facc[i][1] = fma2(hs, w1v, facc[i][1]);
                }
            }
        }
        __syncthreads();
    }

    // ---- epilogue: + b2 + residual(attn_out), store ----
    if (tgf < 10) {
        float4 bb = *(const float4*)(b2 + cgf*4);
        #pragma unroll
        for (int i=0;i<5;i++) {
            int t = tgf*5 + i;
            if (t < 49) {
                int r = t / 7, s = t - r*7;
                const float* ao = Qs + t*QSTR + cgf*4;
                float l0,h0,l1,h1;
                up2(facc[i][0], l0, h0);
                up2(facc[i][1], l1, h1);
                float4 o;
                o.x = l0 + bb.x + ao[0];
                o.y = h0 + bb.y + ao[1];
                o.z = l1 + bb.z + ao[2];
                o.w = h1 + bb.w + ao[3];
                *(float4*)(out + base + (size_t)(r*HW + s)*C + cgf*4) = o;
            }
        }
    }
}

extern "C" void kernel_launch(void* const* d_in, const int* in_sizes, int n_in,
                              void* d_out, int out_size) {
    cudaFuncSetAttribute(swin_fused, cudaFuncAttributeMaxDynamicSharedMemorySize, SMEM_BYTES);
    swin_fused<<<8192, 256, SMEM_BYTES>>>(
        (const float*)d_in[0], (const float*)d_in[1], (const float*)d_in[2],
        (const float*)d_in[3], (const float*)d_in[4], (const float*)d_in[5],
        (const float*)d_in[6], (const float*)d_in[7], (float*)d_out);
}